// round 2
// baseline (speedup 1.0000x reference)
#include <cuda_runtime.h>

// out[b,s,o] = sum_d x[b,s,d] * E[d,o] + bias[o]
// E[d,o] = W[o,d] + ALPHA * sum_c Left[d,c] * Right[c,o]
// Left folds m-cores (core0,core1,core2), Right folds n-cores (core3,core4,core5).

#define ALPHA 16.0f
#define DDIM 1024
#define MROWS 16384   // B*S = 8*2048

// Scratch (no cudaMalloc allowed)
__device__ float g_Left[DDIM * 8];     // Left[d][c]
__device__ float g_Right[8 * DDIM];    // Right[c][o]
__device__ float g_E[DDIM * DDIM];     // E[d][o]

// ---------------------------------------------------------------------------
// Kernel 1: fold TT cores into Left (1024x8) and Right (8x1024). One block.
// ---------------------------------------------------------------------------
__global__ void build_lr(const float* __restrict__ c0, const float* __restrict__ c1,
                         const float* __restrict__ c2, const float* __restrict__ c3,
                         const float* __restrict__ c4, const float* __restrict__ c5) {
    __shared__ float P[8 * 16 * 8];   // P[m1][m2][b] = sum_a c0[m1,a]*c1[a,m2,b]
    __shared__ float S1[8 * 16 * 8];  // S1[e][n2][n3] = sum_f c4[e,n2,f]*c5[f,n3]
    int t = threadIdx.x;

    for (int i = t; i < 8 * 16 * 8; i += blockDim.x) {
        int b = i & 7, m2 = (i >> 3) & 15, m1 = i >> 7;
        float s = 0.f;
        #pragma unroll
        for (int a = 0; a < 8; a++) s += c0[m1 * 8 + a] * c1[(a * 16 + m2) * 8 + b];
        P[i] = s;
    }
    for (int i = t; i < 8 * 16 * 8; i += blockDim.x) {
        int n3 = i & 7, n2 = (i >> 3) & 15, e = i >> 7;
        float s = 0.f;
        #pragma unroll
        for (int f = 0; f < 8; f++) s += c4[(e * 16 + n2) * 8 + f] * c5[f * 8 + n3];
        S1[i] = s;
    }
    __syncthreads();

    // Left[d][c], d = m3*128 + m2*8 + m1
    for (int i = t; i < DDIM * 8; i += blockDim.x) {
        int c = i & 7;
        int d = i >> 3;
        int m1 = d & 7, m2 = (d >> 3) & 15, m3 = d >> 7;
        float s = 0.f;
        #pragma unroll
        for (int b = 0; b < 8; b++) s += P[(m1 * 16 + m2) * 8 + b] * c2[(b * 8 + m3) * 8 + c];
        g_Left[i] = s;
    }
    // Right[c][o], o = n1*128 + n2*8 + n3
    for (int i = t; i < 8 * DDIM; i += blockDim.x) {
        int o = i & 1023;
        int c = i >> 10;
        int n3 = o & 7, n2 = (o >> 3) & 15, n1 = o >> 7;
        float s = 0.f;
        #pragma unroll
        for (int e = 0; e < 8; e++) s += c3[(c * 8 + n1) * 8 + e] * S1[(e * 16 + n2) * 8 + n3];
        g_Right[i] = s;
    }
}

// ---------------------------------------------------------------------------
// Kernel 2: E[d][o] = W[o][d] + ALPHA * Left[d,:] @ Right[:,o]
// ---------------------------------------------------------------------------
__global__ void build_E(const float* __restrict__ W) {
    int idx = blockIdx.x * blockDim.x + threadIdx.x;  // over 1024*1024
    int o = idx & 1023;
    int d = idx >> 10;
    float s = 0.f;
    #pragma unroll
    for (int c = 0; c < 8; c++) s += g_Left[d * 8 + c] * g_Right[c * 1024 + o];
    g_E[idx] = W[o * 1024 + d] + ALPHA * s;
}

// ---------------------------------------------------------------------------
// Kernel 3: C[16384,1024] = X[16384,1024] @ E[1024,1024] + bias
// Classic 128x128 block tile, BK=16, 256 threads, 8x8 per thread, fp32 exact.
// ---------------------------------------------------------------------------
#define BM 128
#define BN 128
#define BK 16
#define TM 8
#define TN 8

__global__ __launch_bounds__(256, 2)
void gemm_bias(const float* __restrict__ X, const float* __restrict__ bias,
               float* __restrict__ out) {
    __shared__ float As[BK][BM];   // transposed A tile
    __shared__ float Bs[BK][BN];
    const int K = 1024, N = 1024;
    const int bx = blockIdx.x;     // N tile index
    const int by = blockIdx.y;     // M tile index
    const int t = threadIdx.x;
    const int tx = t & 15;         // 0..15 -> N micro
    const int ty = t >> 4;         // 0..15 -> M micro

    const float* Xb = X + (size_t)(by * BM) * K;
    const float* Eb = g_E + bx * BN;

    float acc[TM][TN] = {};

    const int arow  = t >> 2;      // 0..63 (two passes cover 128 rows)
    const int acol4 = t & 3;       // float4 slot within BK=16
    const int brow  = t >> 5;      // 0..7 (two passes cover 16 rows)
    const int bcol4 = t & 31;      // float4 slot within BN=128

    for (int k0 = 0; k0 < K; k0 += BK) {
        #pragma unroll
        for (int p = 0; p < 2; p++) {
            int r = arow + p * 64;
            float4 v = *(const float4*)(Xb + (size_t)r * K + k0 + acol4 * 4);
            As[acol4 * 4 + 0][r] = v.x;
            As[acol4 * 4 + 1][r] = v.y;
            As[acol4 * 4 + 2][r] = v.z;
            As[acol4 * 4 + 3][r] = v.w;
        }
        #pragma unroll
        for (int p = 0; p < 2; p++) {
            int r = brow + p * 8;
            float4 v = *(const float4*)(Eb + (size_t)(k0 + r) * N + bcol4 * 4);
            *(float4*)(&Bs[r][bcol4 * 4]) = v;
        }
        __syncthreads();

        #pragma unroll
        for (int k = 0; k < BK; k++) {
            float a[TM], bb[TN];
            #pragma unroll
            for (int i = 0; i < TM; i++) a[i] = As[k][ty * TM + i];
            #pragma unroll
            for (int j = 0; j < TN; j++) bb[j] = Bs[k][tx * TN + j];
            #pragma unroll
            for (int i = 0; i < TM; i++)
                #pragma unroll
                for (int j = 0; j < TN; j++)
                    acc[i][j] += a[i] * bb[j];
        }
        __syncthreads();
    }

    #pragma unroll
    for (int i = 0; i < TM; i++) {
        int row = by * BM + ty * TM + i;
        #pragma unroll
        for (int j = 0; j < TN; j += 4) {
            int col = bx * BN + tx * TN + j;
            float4 v;
            v.x = acc[i][j + 0] + bias[col + 0];
            v.y = acc[i][j + 1] + bias[col + 1];
            v.z = acc[i][j + 2] + bias[col + 2];
            v.w = acc[i][j + 3] + bias[col + 3];
            *(float4*)(out + (size_t)row * N + col) = v;
        }
    }
}

// ---------------------------------------------------------------------------
extern "C" void kernel_launch(void* const* d_in, const int* in_sizes, int n_in,
                              void* d_out, int out_size) {
    const float* x  = (const float*)d_in[0];  // [8,2048,1024]
    const float* W  = (const float*)d_in[1];  // [1024,1024]
    const float* b  = (const float*)d_in[2];  // [1024]
    const float* c0 = (const float*)d_in[3];  // (1,8,8)
    const float* c1 = (const float*)d_in[4];  // (8,16,8)
    const float* c2 = (const float*)d_in[5];  // (8,8,8)
    const float* c3 = (const float*)d_in[6];  // (8,8,8)
    const float* c4 = (const float*)d_in[7];  // (8,16,8)
    const float* c5 = (const float*)d_in[8];  // (8,8,1)
    float* out = (float*)d_out;

    build_lr<<<1, 256>>>(c0, c1, c2, c3, c4, c5);
    build_E<<<(DDIM * DDIM) / 256, 256>>>(W);

    dim3 grid(DDIM / BN, MROWS / BM);   // (8, 128)
    gemm_bias<<<grid, 256>>>(x, b, out);
}

// round 4
// speedup vs baseline: 3.5014x; 3.5014x over previous
#include <cuda_runtime.h>
#include <cstdint>

#define ALPHA 16.0f
#define DDIM  1024
#define MROWS 16384   // B*S

// ---------------- scratch (no cudaMalloc allowed) ----------------
__device__ float g_Left[DDIM * 8];
__device__ float g_Right[8 * DDIM];
__device__ float g_E[DDIM * DDIM];      // tf32-rounded E[d][o]

// ---------------- helpers ----------------
__device__ __forceinline__ uint32_t smem_u32(const void* p) {
    uint32_t a;
    asm("{ .reg .u64 t; cvta.to.shared.u64 t, %1; cvt.u32.u64 %0, t; }" : "=r"(a) : "l"(p));
    return a;
}
__device__ __forceinline__ float to_tf32_f(float v) {
    asm("cvt.rna.tf32.f32 %0, %1;" : "=f"(v) : "f"(v));
    return v;
}
__device__ __forceinline__ uint32_t to_tf32_u(float f) {
    uint32_t u;
    asm("cvt.rna.tf32.f32 %0, %1;" : "=r"(u) : "f"(f));
    return u;
}
__device__ __forceinline__ void cp16(void* dst_smem, const void* src) {
    uint32_t d = smem_u32(dst_smem);
    asm volatile("cp.async.cg.shared.global [%0], [%1], 16;" :: "r"(d), "l"(src) : "memory");
}
#define CP_COMMIT()  asm volatile("cp.async.commit_group;" ::: "memory")
#define CP_WAIT(n)   asm volatile("cp.async.wait_group %0;" :: "n"(n) : "memory")

__device__ __forceinline__ void mma_tf32(float* c, const uint32_t* a, const uint32_t* b) {
    asm volatile(
        "mma.sync.aligned.m16n8k8.row.col.f32.tf32.tf32.f32 "
        "{%0,%1,%2,%3}, {%4,%5,%6,%7}, {%8,%9}, {%0,%1,%2,%3};"
        : "+f"(c[0]), "+f"(c[1]), "+f"(c[2]), "+f"(c[3])
        : "r"(a[0]), "r"(a[1]), "r"(a[2]), "r"(a[3]), "r"(b[0]), "r"(b[1]));
}

// ---------------------------------------------------------------------------
// Kernel 1: fold TT cores into Left (1024x8) and Right (8x1024). SMEM-staged.
// ---------------------------------------------------------------------------
__global__ void build_lr(const float* __restrict__ c0, const float* __restrict__ c1,
                         const float* __restrict__ c2, const float* __restrict__ c3,
                         const float* __restrict__ c4, const float* __restrict__ c5) {
    __shared__ float C0[64], C1[1024], C2[512], C3[512], C4[1024], C5[64];
    __shared__ float P[1024], S1[1024];
    int t = threadIdx.x;
    for (int i = t; i < 64;   i += blockDim.x) C0[i] = c0[i];
    for (int i = t; i < 1024; i += blockDim.x) C1[i] = c1[i];
    for (int i = t; i < 512;  i += blockDim.x) C2[i] = c2[i];
    for (int i = t; i < 512;  i += blockDim.x) C3[i] = c3[i];
    for (int i = t; i < 1024; i += blockDim.x) C4[i] = c4[i];
    for (int i = t; i < 64;   i += blockDim.x) C5[i] = c5[i];
    __syncthreads();

    for (int i = t; i < 1024; i += blockDim.x) {
        int b = i & 7, m2 = (i >> 3) & 15, m1 = i >> 7;
        float s = 0.f;
        #pragma unroll
        for (int a = 0; a < 8; a++) s += C0[m1 * 8 + a] * C1[(a * 16 + m2) * 8 + b];
        P[i] = s;
    }
    for (int i = t; i < 1024; i += blockDim.x) {
        int n3 = i & 7, n2 = (i >> 3) & 15, e = i >> 7;
        float s = 0.f;
        #pragma unroll
        for (int f = 0; f < 8; f++) s += C4[(e * 16 + n2) * 8 + f] * C5[f * 8 + n3];
        S1[i] = s;
    }
    __syncthreads();

    for (int i = t; i < DDIM * 8; i += blockDim.x) {
        int c = i & 7;  int d = i >> 3;
        int m1 = d & 7, m2 = (d >> 3) & 15, m3 = d >> 7;
        float s = 0.f;
        #pragma unroll
        for (int b = 0; b < 8; b++) s += P[(m1 * 16 + m2) * 8 + b] * C2[(b * 8 + m3) * 8 + c];
        g_Left[i] = s;
    }
    for (int i = t; i < 8 * DDIM; i += blockDim.x) {
        int o = i & 1023;  int c = i >> 10;
        int n3 = o & 7, n2 = (o >> 3) & 15, n1 = o >> 7;
        float s = 0.f;
        #pragma unroll
        for (int e = 0; e < 8; e++) s += C3[(c * 8 + n1) * 8 + e] * S1[(e * 16 + n2) * 8 + n3];
        g_Right[i] = s;
    }
}

// ---------------------------------------------------------------------------
// Kernel 2: E[d][o] = tf32_round( W[o][d] + ALPHA * Left[d,:] @ Right[:,o] )
// Pre-rounding makes the GEMM's B operand exact under the mma's tf32 read.
// ---------------------------------------------------------------------------
__global__ void build_E(const float* __restrict__ W) {
    int idx = blockIdx.x * blockDim.x + threadIdx.x;
    int o = idx & 1023;
    int d = idx >> 10;
    float s = 0.f;
    #pragma unroll
    for (int c = 0; c < 8; c++) s += g_Left[d * 8 + c] * g_Right[c * 1024 + o];
    g_E[idx] = to_tf32_f(W[o * 1024 + d] + ALPHA * s);
}

// ---------------------------------------------------------------------------
// Kernel 3: tf32 mma.sync GEMM. C[16384,1024] = X @ E + bias.
// BM=BN=128, BK=32, 256 threads (8 warps, 4x2), 2-stage cp.async pipeline.
// A smem [128][36] (pad 4 -> frag banks 4g+tig, conflict-free)
// B smem [32][136] (pad 8 -> frag banks 8*tig+g, conflict-free)
// ---------------------------------------------------------------------------
#define ASTRIDE 36
#define BSTRIDE 136
#define A_STG   (128 * ASTRIDE)   // floats per stage
#define B_STG   (32 * BSTRIDE)
#define NCHUNK  32

__global__ __launch_bounds__(256, 2)
void gemm_tf32(const float* __restrict__ X, const float* __restrict__ bias,
               float* __restrict__ out) {
    extern __shared__ float sm[];
    float* As = sm;                 // 2 stages
    float* Bs = sm + 2 * A_STG;

    const int t    = threadIdx.x;
    const int wid  = t >> 5;
    const int lane = t & 31;
    const int g    = lane >> 2;     // 0..7
    const int tig  = lane & 3;      // 0..3
    const int wm   = wid >> 1;      // 0..3  (32-row band)
    const int wn   = wid & 1;       // 0..1  (64-col band)
    const int bx   = blockIdx.x;    // N tile (0..7)
    const int by   = blockIdx.y;    // M tile (0..127)

    const float* Xb = X + (size_t)(by * 128) * 1024;
    const float* Eb = g_E + bx * 128;

    // cp.async assignments
    const int a_row = t >> 1;            // qi = t + p*256 -> row = qi>>3 ... recompute per p
    (void)a_row;

    float acc[2][8][4];
    #pragma unroll
    for (int mt = 0; mt < 2; mt++)
        #pragma unroll
        for (int nt = 0; nt < 8; nt++)
            #pragma unroll
            for (int i = 0; i < 4; i++) acc[mt][nt][i] = 0.f;

    // ---- stage loader ----
    auto load_stage = [&](int s, int kc) {
        float* Ad = As + s * A_STG;
        float* Bd = Bs + s * B_STG;
        #pragma unroll
        for (int p = 0; p < 4; p++) {
            int qi = t + p * 256;           // 0..1023
            int row = qi >> 3, quad = qi & 7;
            cp16(Ad + row * ASTRIDE + quad * 4,
                 Xb + (size_t)row * 1024 + kc + quad * 4);
        }
        #pragma unroll
        for (int p = 0; p < 4; p++) {
            int qi = t + p * 256;
            int row = qi >> 5, quad = qi & 31;
            cp16(Bd + row * BSTRIDE + quad * 4,
                 Eb + (size_t)(kc + row) * 1024 + quad * 4);
        }
    };

    load_stage(0, 0);
    CP_COMMIT();

    for (int c = 0; c < NCHUNK; c++) {
        if (c < NCHUNK - 1) {
            load_stage((c + 1) & 1, (c + 1) * 32);
            CP_COMMIT();
            CP_WAIT(1);
        } else {
            CP_WAIT(0);
        }
        __syncthreads();

        const float* Ab = As + (c & 1) * A_STG;
        const float* Bb = Bs + (c & 1) * B_STG;

        #pragma unroll
        for (int ks = 0; ks < 4; ks++) {
            const int k = ks * 8;
            uint32_t af[2][4];
            #pragma unroll
            for (int mt = 0; mt < 2; mt++) {
                int m = wm * 32 + mt * 16;
                af[mt][0] = to_tf32_u(Ab[(m + g)     * ASTRIDE + k + tig]);
                af[mt][1] = to_tf32_u(Ab[(m + g + 8) * ASTRIDE + k + tig]);
                af[mt][2] = to_tf32_u(Ab[(m + g)     * ASTRIDE + k + tig + 4]);
                af[mt][3] = to_tf32_u(Ab[(m + g + 8) * ASTRIDE + k + tig + 4]);
            }
            #pragma unroll
            for (int nt = 0; nt < 8; nt++) {
                int n = wn * 64 + nt * 8;
                uint32_t bf[2];
                bf[0] = __float_as_uint(Bb[(k + tig)     * BSTRIDE + n + g]);
                bf[1] = __float_as_uint(Bb[(k + tig + 4) * BSTRIDE + n + g]);
                mma_tf32(acc[0][nt], af[0], bf);
                mma_tf32(acc[1][nt], af[1], bf);
            }
        }
        __syncthreads();
    }

    // ---- epilogue: bias add, direct stores (float2 per fragment row) ----
    #pragma unroll
    for (int mt = 0; mt < 2; mt++) {
        int row0 = by * 128 + wm * 32 + mt * 16 + g;
        #pragma unroll
        for (int nt = 0; nt < 8; nt++) {
            int col = bx * 128 + wn * 64 + nt * 8 + tig * 2;
            float b0 = bias[col], b1 = bias[col + 1];
            float2 v0 = { acc[mt][nt][0] + b0, acc[mt][nt][1] + b1 };
            float2 v1 = { acc[mt][nt][2] + b0, acc[mt][nt][3] + b1 };
            *(float2*)(out + (size_t)row0 * 1024 + col)       = v0;
            *(float2*)(out + (size_t)(row0 + 8) * 1024 + col) = v1;
        }
    }
}

// ---------------------------------------------------------------------------
extern "C" void kernel_launch(void* const* d_in, const int* in_sizes, int n_in,
                              void* d_out, int out_size) {
    const float* x  = (const float*)d_in[0];
    const float* W  = (const float*)d_in[1];
    const float* b  = (const float*)d_in[2];
    const float* c0 = (const float*)d_in[3];
    const float* c1 = (const float*)d_in[4];
    const float* c2 = (const float*)d_in[5];
    const float* c3 = (const float*)d_in[6];
    const float* c4 = (const float*)d_in[7];
    const float* c5 = (const float*)d_in[8];
    float* out = (float*)d_out;

    build_lr<<<1, 256>>>(c0, c1, c2, c3, c4, c5);
    build_E<<<(DDIM * DDIM) / 256, 256>>>(W);

    const int smem_bytes = (2 * A_STG + 2 * B_STG) * 4;   // ~70 KB
    cudaFuncSetAttribute(gemm_tf32, cudaFuncAttributeMaxDynamicSharedMemorySize, smem_bytes);
    dim3 grid(8, 128);   // (N tiles, M tiles), bx fastest: concurrent CTAs share A band
    gemm_tf32<<<grid, 256, smem_bytes>>>(x, b, out);
}